// round 4
// baseline (speedup 1.0000x reference)
#include <cuda_runtime.h>
#include <cuda_bf16.h>
#include <stdint.h>

// Problem constants
#define S_TOTAL   4096
#define W_WIDTH   16
#define N_NODES   193
#define NDIM      2
#define P_ORDER   4
#define ROW_F     (N_NODES * NDIM)                        // 386 floats per (s,w) row
#define BLK_F     (W_WIDTH * ROW_F)                       // 6176 floats per (array,sample)
#define BLK_F4    (BLK_F / 4)                             // 1544 float4
#define SCAT_ELEMS (S_TOTAL * W_WIDTH * N_NODES * NDIM)   // 25,296,896

// Output layout (float offsets), reference return order
#define OFF_T     0
#define OFF_DT    (S_TOTAL * W_WIDTH)                     // 65536
#define OFF_DDT   (2 * S_TOTAL * W_WIDTH)                 // 131072
#define OFF_PHI   (3 * S_TOTAL * W_WIDTH)                 // 196608
#define OFF_DX    (OFF_PHI + 3 * SCAT_ELEMS)              // 76,087,296

#define DELTA_X 0.0078125f                                // 1/128 exactly
#define INV_DX  128.0f
#define INV_DX2 16384.0f

#define GRID_CTAS 1216                                    // 152 SMs x 8
#define MAX_Q     4                                       // ceil(4096/1216)

__global__ __launch_bounds__(256)
void lagr_kann_kernel(const float* __restrict__ x,
                      const float* __restrict__ weight,
                      float* __restrict__ out)
{
    const int tid = threadIdx.x;
    const int s0  = blockIdx.x;

    __shared__ int   scol[MAX_Q][8];        // scatter column per (d,j): e = d*4 + j
    __shared__ float sval[MAX_Q][3][8];     // phi / dphi / ddphi values

    // ---- phase 1: 32 threads compute basis for all owned samples ----
    if (tid < 32) {
        const int q = tid >> 3;
        const int e = tid & 7;
        const int s = s0 + q * GRID_CTAS;
        if (s < S_TOTAL) {
            const int dd = e >> 2;
            const int jj = e & 3;
            const float xv = x[s * 2 + dd];
            const float xs = 192.0f * xv;                  // x_shift
            float fel = floorf(xs / 3.0f);
            fel = fminf(fmaxf(fel, 0.0f), 63.0f);
            const int nl = (int)(fel * 3.0f);              // left node index
            const float xr = 2.0f * (xs - (float)nl) / 3.0f - 1.0f;

            const float nodes[4] = { -1.0f, -1.0f / 3.0f, 1.0f / 3.0f, 1.0f };

            // value
            float pv;
            {
                float p = 1.0f;
                #pragma unroll
                for (int m = 0; m < P_ORDER; m++)
                    if (m != jj) p *= (xr - nodes[m]) / (nodes[jj] - nodes[m]);
                pv = p;
            }
            // first derivative
            float dv;
            {
                float y1 = 0.0f;
                #pragma unroll
                for (int i2 = 0; i2 < P_ORDER; i2++) {
                    if (i2 == jj) continue;
                    float k = 1.0f / (nodes[jj] - nodes[i2]);
                    #pragma unroll
                    for (int m = 0; m < P_ORDER; m++)
                        if (m != i2 && m != jj) k *= (xr - nodes[m]) / (nodes[jj] - nodes[m]);
                    y1 += k;
                }
                dv = y1 * INV_DX;
            }
            // second derivative
            float ddv;
            {
                float y2 = 0.0f;
                #pragma unroll
                for (int i2 = 0; i2 < P_ORDER; i2++) {
                    if (i2 == jj) continue;
                    float ks = 0.0f;
                    #pragma unroll
                    for (int m = 0; m < P_ORDER; m++) {
                        if (m == i2 || m == jj) continue;
                        float kp = 1.0f / (nodes[jj] - nodes[m]);
                        #pragma unroll
                        for (int n = 0; n < P_ORDER; n++)
                            if (n != i2 && n != jj && n != m)
                                kp *= (xr - nodes[n]) / (nodes[jj] - nodes[n]);
                        ks += kp;
                    }
                    y2 += ks / (nodes[jj] - nodes[i2]);
                }
                ddv = y2 * INV_DX2;
            }

            scol[q][e]    = (nl + jj) * 2 + dd;
            sval[q][0][e] = pv;
            sval[q][1][e] = dv;
            sval[q][2][e] = ddv;
        }
    }

    // ---- phase 2: continuous zero-fill of all owned blocks (streaming float4) ----
    const float4 z = make_float4(0.0f, 0.0f, 0.0f, 0.0f);
    #pragma unroll
    for (int q = 0; q < MAX_Q; q++) {
        const int s = s0 + q * GRID_CTAS;
        if (s >= S_TOTAL) break;
        float4* p0 = (float4*)(out + OFF_PHI) + (size_t)s * BLK_F4;
        float4* p1 = p0 + (size_t)(SCAT_ELEMS / 4);
        float4* p2 = p1 + (size_t)(SCAT_ELEMS / 4);
        for (int i = tid; i < BLK_F4; i += 256) {
            __stcs(p0 + i, z);
            __stcs(p1 + i, z);
            __stcs(p2 + i, z);
        }
    }

    __syncthreads();   // zero-fill done (CTA-wide); sval/scol visible

    // ---- phase 3: 400 work items over 256 threads ----
    //      items 0..383: scatter nonzeros; items 384..399: einsum per width k
    #pragma unroll
    for (int q = 0; q < MAX_Q; q++) {
        const int s = s0 + q * GRID_CTAS;
        if (s >= S_TOTAL) break;
        for (int idx = tid; idx < 400; idx += 256) {
            if (idx < 384) {
                const int a = idx >> 7;          // array 0..2
                const int r = idx & 127;
                const int w = r >> 3;            // width 0..15
                const int e = r & 7;             // basis entry 0..7
                float* base = out + OFF_PHI + (size_t)s * BLK_F;
                base[(size_t)a * SCAT_ELEMS + w * ROW_F + scol[q][e]] = sval[q][a][e];
            } else {
                const int k = idx - 384;         // width 0..15
                const float* wk = weight + k * ROW_F;
                float t = 0.0f, dt = 0.0f, ddt = 0.0f;
                #pragma unroll
                for (int e = 0; e < 8; e++) {
                    const float wv = wk[scol[q][e]];
                    t   += wv * sval[q][0][e];
                    dt  += wv * sval[q][1][e];
                    ddt += wv * sval[q][2][e];
                }
                out[OFF_T   + s * W_WIDTH + k] = t;
                out[OFF_DT  + s * W_WIDTH + k] = dt;
                out[OFF_DDT + s * W_WIDTH + k] = ddt;
            }
        }
    }

    // ---- delta_x scalar ----
    if (s0 == 0 && tid == 0) out[OFF_DX] = DELTA_X;
}

extern "C" void kernel_launch(void* const* d_in, const int* in_sizes, int n_in,
                              void* d_out, int out_size)
{
    const float* x      = (const float*)d_in[0];   // (4096, 2)
    const float* weight = (const float*)d_in[1];   // (16, 193, 2)
    float* out = (float*)d_out;
    lagr_kann_kernel<<<GRID_CTAS, 256>>>(x, weight, out);
}

// round 5
// speedup vs baseline: 1.1916x; 1.1916x over previous
#include <cuda_runtime.h>
#include <cuda_bf16.h>
#include <stdint.h>

// Problem constants
#define S_TOTAL   4096
#define W_WIDTH   16
#define N_NODES   193
#define NDIM      2
#define P_ORDER   4
#define ROW_F     (N_NODES * NDIM)                        // 386 floats per (s,w) row
#define UNIT_F    (2 * ROW_F)                             // 772 floats = 2 rows = 193 float4
#define UNIT_F4   (UNIT_F / 4)                            // 193
#define BLK_F     (W_WIDTH * ROW_F)                       // 6176 floats per (array,sample)
#define BLK_F4    (BLK_F / 4)                             // 1544 float4 = 8 units
#define SCAT_ELEMS (S_TOTAL * W_WIDTH * N_NODES * NDIM)   // 25,296,896

// Output layout (float offsets), reference return order
#define OFF_T     0
#define OFF_DT    (S_TOTAL * W_WIDTH)                     // 65536
#define OFF_DDT   (2 * S_TOTAL * W_WIDTH)                 // 131072
#define OFF_PHI   (3 * S_TOTAL * W_WIDTH)                 // 196608 (float4-aligned)
#define OFF_DX    (OFF_PHI + 3 * SCAT_ELEMS)              // 76,087,296

#define DELTA_X 0.0078125f                                // 1/128 exactly
#define INV_DX  128.0f
#define INV_DX2 16384.0f

__global__ __launch_bounds__(256)
void lagr_kann_kernel(const float* __restrict__ x,
                      const float* __restrict__ weight,
                      float* __restrict__ out)
{
    const int s   = blockIdx.x;
    const int tid = threadIdx.x;

    // Staged double-row (2 identical 386-float rows) per array, nonzeros embedded.
    __shared__ __align__(16) float drow[3][UNIT_F];   // 3 x 772 floats
    __shared__ int scol[8];                           // nonzero column per (d,j)

    // ---- zero the staged double-rows (float4) ----
    {
        float4* d4 = (float4*)&drow[0][0];            // 3*193 = 579 float4
        const float4 z = make_float4(0.0f, 0.0f, 0.0f, 0.0f);
        for (int i = tid; i < 3 * UNIT_F4; i += 256) d4[i] = z;
    }
    __syncthreads();

    // ---- 8 threads compute the Lagrange basis (d = tid>>2, j = tid&3) ----
    if (tid < 8) {
        const int dd = tid >> 2;
        const int jj = tid & 3;
        const float xv = x[s * 2 + dd];
        const float xs = 192.0f * xv;                  // x_shift
        float fel = floorf(xs / 3.0f);
        fel = fminf(fmaxf(fel, 0.0f), 63.0f);
        const int nl = (int)(fel * 3.0f);              // left node index
        const float xr = 2.0f * (xs - (float)nl) / 3.0f - 1.0f;

        const float nodes[4] = { -1.0f, -1.0f / 3.0f, 1.0f / 3.0f, 1.0f };

        // value
        float pv;
        {
            float p = 1.0f;
            #pragma unroll
            for (int m = 0; m < P_ORDER; m++)
                if (m != jj) p *= (xr - nodes[m]) / (nodes[jj] - nodes[m]);
            pv = p;
        }
        // first derivative
        float dv;
        {
            float y1 = 0.0f;
            #pragma unroll
            for (int i2 = 0; i2 < P_ORDER; i2++) {
                if (i2 == jj) continue;
                float k = 1.0f / (nodes[jj] - nodes[i2]);
                #pragma unroll
                for (int m = 0; m < P_ORDER; m++)
                    if (m != i2 && m != jj) k *= (xr - nodes[m]) / (nodes[jj] - nodes[m]);
                y1 += k;
            }
            dv = y1 * INV_DX;
        }
        // second derivative
        float ddv;
        {
            float y2 = 0.0f;
            #pragma unroll
            for (int i2 = 0; i2 < P_ORDER; i2++) {
                if (i2 == jj) continue;
                float ks = 0.0f;
                #pragma unroll
                for (int m = 0; m < P_ORDER; m++) {
                    if (m == i2 || m == jj) continue;
                    float kp = 1.0f / (nodes[jj] - nodes[m]);
                    #pragma unroll
                    for (int n = 0; n < P_ORDER; n++)
                        if (n != i2 && n != jj && n != m)
                            kp *= (xr - nodes[n]) / (nodes[jj] - nodes[n]);
                    ks += kp;
                }
                y2 += ks / (nodes[jj] - nodes[i2]);
            }
            ddv = y2 * INV_DX2;
        }

        const int col = (nl + jj) * 2 + dd;
        scol[tid] = col;
        // embed nonzeros into both rows of the double-row unit
        drow[0][col] = pv;   drow[0][col + ROW_F] = pv;
        drow[1][col] = dv;   drow[1][col + ROW_F] = dv;
        drow[2][col] = ddv;  drow[2][col + ROW_F] = ddv;
    }
    __syncthreads();   // drow complete, scol visible

    // ---- einsum reductions: 16 threads, one per width k ----
    if (tid < 16) {
        const int k = tid;
        const float* wk = weight + k * ROW_F;
        float t = 0.0f, dt = 0.0f, ddt = 0.0f;
        #pragma unroll
        for (int e = 0; e < 8; e++) {
            const int c = scol[e];
            const float wv = wk[c];
            t   += wv * drow[0][c];
            dt  += wv * drow[1][c];
            ddt += wv * drow[2][c];
        }
        out[OFF_T   + s * W_WIDTH + k] = t;
        out[OFF_DT  + s * W_WIDTH + k] = dt;
        out[OFF_DDT + s * W_WIDTH + k] = ddt;
    }

    // ---- single-pass fill: 8 copies of the double-row unit per array ----
    // dst offset within block is linear in idx; src index is idx mod 193,
    // maintained incrementally (stride 256 mod 193 == +63).
    {
        const float4* src = (const float4*)&drow[0][0];       // [3][193]
        float4* dst = (float4*)out + (OFF_PHI / 4);
        const int i0 = tid % 193;
        #pragma unroll
        for (int a = 0; a < 3; a++) {
            float4* d = dst + (size_t)a * (SCAT_ELEMS / 4) + (size_t)s * BLK_F4;
            const float4* sr = src + a * UNIT_F4;
            int i = i0;
            for (int idx = tid; idx < BLK_F4; idx += 256) {
                d[idx] = sr[i];
                i += 63; if (i >= 193) i -= 193;
            }
        }
    }

    // ---- delta_x scalar ----
    if (s == 0 && tid == 32) out[OFF_DX] = DELTA_X;
}

extern "C" void kernel_launch(void* const* d_in, const int* in_sizes, int n_in,
                              void* d_out, int out_size)
{
    const float* x      = (const float*)d_in[0];   // (4096, 2)
    const float* weight = (const float*)d_in[1];   // (16, 193, 2)
    float* out = (float*)d_out;
    lagr_kann_kernel<<<S_TOTAL, 256>>>(x, weight, out);
}

// round 6
// speedup vs baseline: 1.3489x; 1.1320x over previous
#include <cuda_runtime.h>
#include <cuda_bf16.h>
#include <stdint.h>

// Problem constants
#define S_TOTAL   4096
#define W_WIDTH   16
#define N_NODES   193
#define NDIM      2
#define P_ORDER   4
#define ROW_F     (N_NODES * NDIM)                        // 386 floats per (s,w) row
#define BLK_F     (W_WIDTH * ROW_F)                       // 6176 floats per (array,sample)
#define BLK_F4    (BLK_F / 4)                             // 1544 float4
#define SCAT_ELEMS (S_TOTAL * W_WIDTH * N_NODES * NDIM)   // 25,296,896

// Output layout (float offsets), reference return order
#define OFF_T     0
#define OFF_DT    (S_TOTAL * W_WIDTH)                     // 65536
#define OFF_DDT   (2 * S_TOTAL * W_WIDTH)                 // 131072
#define OFF_PHI   (3 * S_TOTAL * W_WIDTH)                 // 196608 (float4-aligned)
#define OFF_DX    (OFF_PHI + 3 * SCAT_ELEMS)              // 76,087,296

#define DELTA_X 0.0078125f                                // 1/128 exactly
#define INV_DX  128.0f
#define INV_DX2 16384.0f

__global__ __launch_bounds__(256)
void lagr_kann_kernel(const float* __restrict__ x,
                      const float* __restrict__ weight,
                      float* __restrict__ out)
{
    const int s   = blockIdx.x;
    const int tid = threadIdx.x;

    __shared__ int   scol[8];        // scatter column per (d,j): e = d*4 + j
    __shared__ float sval[3][8];     // phi / dphi / ddphi values

    // ---- warp 0, 8 threads: Lagrange basis (d = tid>>2, j = tid&3) ----
    if (tid < 8) {
        const int dd = tid >> 2;
        const int jj = tid & 3;
        const float xv = x[s * 2 + dd];
        const float xs = 192.0f * xv;                      // x_shift
        float fel = floorf(xs / 3.0f);
        fel = fminf(fmaxf(fel, 0.0f), 63.0f);
        const int nl = (int)(fel * 3.0f);                  // left node index
        const float xr = 2.0f * (xs - (float)nl) / 3.0f - 1.0f;

        const float nodes[4] = { -1.0f, -1.0f / 3.0f, 1.0f / 3.0f, 1.0f };

        float pv;
        {
            float p = 1.0f;
            #pragma unroll
            for (int m = 0; m < P_ORDER; m++)
                if (m != jj) p *= (xr - nodes[m]) / (nodes[jj] - nodes[m]);
            pv = p;
        }
        float dv;
        {
            float y1 = 0.0f;
            #pragma unroll
            for (int i2 = 0; i2 < P_ORDER; i2++) {
                if (i2 == jj) continue;
                float k = 1.0f / (nodes[jj] - nodes[i2]);
                #pragma unroll
                for (int m = 0; m < P_ORDER; m++)
                    if (m != i2 && m != jj) k *= (xr - nodes[m]) / (nodes[jj] - nodes[m]);
                y1 += k;
            }
            dv = y1 * INV_DX;
        }
        float ddv;
        {
            float y2 = 0.0f;
            #pragma unroll
            for (int i2 = 0; i2 < P_ORDER; i2++) {
                if (i2 == jj) continue;
                float ks = 0.0f;
                #pragma unroll
                for (int m = 0; m < P_ORDER; m++) {
                    if (m == i2 || m == jj) continue;
                    float kp = 1.0f / (nodes[jj] - nodes[m]);
                    #pragma unroll
                    for (int n = 0; n < P_ORDER; n++)
                        if (n != i2 && n != jj && n != m)
                            kp *= (xr - nodes[n]) / (nodes[jj] - nodes[n]);
                    ks += kp;
                }
                y2 += ks / (nodes[jj] - nodes[i2]);
            }
            ddv = y2 * INV_DX2;
        }

        scol[tid]    = (nl + jj) * 2 + dd;
        sval[0][tid] = pv;
        sval[1][tid] = dv;
        sval[2][tid] = ddv;
    }

    // ---- bulk zero-fill: fully unrolled, 18 independent STG.128 per thread ----
    {
        const float4 z = make_float4(0.0f, 0.0f, 0.0f, 0.0f);
        float4* p0 = (float4*)(out + OFF_PHI) + (size_t)s * BLK_F4;
        float4* p1 = p0 + (size_t)(SCAT_ELEMS / 4);
        float4* p2 = p1 + (size_t)(SCAT_ELEMS / 4);
        #pragma unroll
        for (int i = 0; i < 6; i++) {
            const int idx = tid + i * 256;
            p0[idx] = z;
            p1[idx] = z;
            p2[idx] = z;
        }
        // tail: 1544 - 6*256 = 8 remaining float4 per array
        if (tid < 8) {
            const int idx = 1536 + tid;
            p0[idx] = z;
            p1[idx] = z;
            p2[idx] = z;
        }
    }

    __syncthreads();   // zero-fill done; sval/scol visible

    // ---- scatter nonzeros + einsum: 400 work items over 256 threads ----
    for (int idx = tid; idx < 400; idx += 256) {
        if (idx < 384) {
            const int a = idx >> 7;          // array 0..2
            const int r = idx & 127;
            const int w = r >> 3;            // width 0..15
            const int e = r & 7;             // basis entry 0..7
            float* base = out + OFF_PHI + (size_t)s * BLK_F;
            base[(size_t)a * SCAT_ELEMS + w * ROW_F + scol[e]] = sval[a][e];
        } else {
            const int k = idx - 384;         // width 0..15
            const float* wk = weight + k * ROW_F;
            float t = 0.0f, dt = 0.0f, ddt = 0.0f;
            #pragma unroll
            for (int e = 0; e < 8; e++) {
                const float wv = wk[scol[e]];
                t   += wv * sval[0][e];
                dt  += wv * sval[1][e];
                ddt += wv * sval[2][e];
            }
            out[OFF_T   + s * W_WIDTH + k] = t;
            out[OFF_DT  + s * W_WIDTH + k] = dt;
            out[OFF_DDT + s * W_WIDTH + k] = ddt;
        }
    }

    // ---- delta_x scalar ----
    if (s == 0 && tid == 64) out[OFF_DX] = DELTA_X;
}

extern "C" void kernel_launch(void* const* d_in, const int* in_sizes, int n_in,
                              void* d_out, int out_size)
{
    const float* x      = (const float*)d_in[0];   // (4096, 2)
    const float* weight = (const float*)d_in[1];   // (16, 193, 2)
    float* out = (float*)d_out;
    lagr_kann_kernel<<<S_TOTAL, 256>>>(x, weight, out);
}